// round 1
// baseline (speedup 1.0000x reference)
#include <cuda_runtime.h>

#define B_SZ   64
#define FEAT   512
#define NB     8
#define H_SZ   1024
#define WR     513            // W/2 + 1
#define HWR    (H_SZ * WR)    // 525312, divisible by 4

// Scratch for band weights between kernels (no cudaMalloc allowed).
__device__ float g_bw[B_SZ * NB];

// ---------------------------------------------------------------------------
// Kernel 1: logits = feat @ w.T + bias ; softmax over 8 bands.
// grid = 64 blocks (one per batch row), 256 threads = 8 warps (one per band).
// ---------------------------------------------------------------------------
__global__ void mlp_softmax_kernel(const float* __restrict__ feat,
                                   const float* __restrict__ w,
                                   const float* __restrict__ bias) {
    const int b    = blockIdx.x;
    const int warp = threadIdx.x >> 5;   // band
    const int lane = threadIdx.x & 31;

    const float* f  = feat + b * FEAT;
    const float* wr = w + warp * FEAT;

    float acc = 0.0f;
    #pragma unroll
    for (int k = lane; k < FEAT; k += 32)
        acc += f[k] * wr[k];

    #pragma unroll
    for (int o = 16; o; o >>= 1)
        acc += __shfl_down_sync(0xffffffffu, acc, o);

    __shared__ float sl[NB];
    __shared__ float se[NB];
    if (lane == 0) sl[warp] = acc + bias[warp];
    __syncthreads();

    if (threadIdx.x < NB) {
        float m = sl[0];
        #pragma unroll
        for (int i = 1; i < NB; i++) m = fmaxf(m, sl[i]);
        se[threadIdx.x] = expf(sl[threadIdx.x] - m);
    }
    __syncthreads();

    if (threadIdx.x < NB) {
        float s = 0.0f;
        #pragma unroll
        for (int i = 0; i < NB; i++) s += se[i];
        g_bw[b * NB + threadIdx.x] = se[threadIdx.x] / s;
    }
}

// ---------------------------------------------------------------------------
// Kernel 2: fill the [64, 1024, 513] output.
// Thread = 4 consecutive pixels in the (h,w)-plane; band index computed once
// per pixel, reused across all 64 batch planes with a float4 store each.
// Shared LUT is [64][9]: slot 8 = 0.0f handles the r == max_r pixel
// (reference masks give 0 there since radius < upper fails for all bands).
// ---------------------------------------------------------------------------
__global__ void fill_kernel(float* __restrict__ out) {
    __shared__ float bw[B_SZ * 9];
    for (int i = threadIdx.x; i < B_SZ * 9; i += blockDim.x) {
        int b = i / 9, s = i - b * 9;
        bw[i] = (s < NB) ? g_bw[b * NB + s] : 0.0f;
    }
    __syncthreads();

    const int tid  = blockIdx.x * blockDim.x + threadIdx.x;
    const int base = tid * 4;
    if (base >= HWR) return;

    const float max_r = sqrtf(0.5f);   // == jnp radius.max(), bit-exact

    int band[4];
    #pragma unroll
    for (int j = 0; j < 4; j++) {
        int p  = base + j;
        int h  = p / WR;
        int wc = p - h * WR;
        float u = (float)wc * (1.0f / 1024.0f);                 // rfftfreq
        float v = (float)(h < H_SZ / 2 ? h : h - H_SZ) * (1.0f / 1024.0f); // fftfreq
        float r = sqrtf(u * u + v * v);                          // exact args

        int bi = 0;
        #pragma unroll
        for (int i = 1; i < NB; i++)
            bi += (r >= max_r * ((float)i / (float)NB)) ? 1 : 0;
        band[j] = (r >= max_r) ? 8 : bi;   // sentinel -> zero slot
    }

    float* o = out + base;
    #pragma unroll 4
    for (int b = 0; b < B_SZ; b++) {
        const float* row = bw + b * 9;
        float4 v4;
        v4.x = row[band[0]];
        v4.y = row[band[1]];
        v4.z = row[band[2]];
        v4.w = row[band[3]];
        *reinterpret_cast<float4*>(o + (size_t)b * HWR) = v4;
    }
}

// ---------------------------------------------------------------------------
extern "C" void kernel_launch(void* const* d_in, const int* in_sizes, int n_in,
                              void* d_out, int out_size) {
    const float* feat = (const float*)d_in[0];  // [64, 512]
    const float* w    = (const float*)d_in[1];  // [8, 512]
    const float* bias = (const float*)d_in[2];  // [8]
    float* out = (float*)d_out;                 // [64, 1, 1024, 513] fp32

    mlp_softmax_kernel<<<B_SZ, 256>>>(feat, w, bias);

    const int n_threads = HWR / 4;              // 131328
    fill_kernel<<<(n_threads + 255) / 256, 256>>>(out);
}

// round 2
// speedup vs baseline: 1.0082x; 1.0082x over previous
#include <cuda_runtime.h>

#define B_SZ   64
#define FEAT   512
#define NB     8
#define H_SZ   1024
#define WR     513            // W/2 + 1
#define HWR    (H_SZ * WR)    // 525312, divisible by 4
#define NQUAD  (HWR / 4)      // 131328
#define TPB    128
#define GRID   (NQUAD / TPB)  // 1026 exactly

// Inter-block handshake state (persists across graph replays; reset in-kernel).
__device__ float g_bw[B_SZ * NB];
__device__ int   g_ready;     // zero-initialized; producers count to 64
__device__ int   g_done;      // zero-initialized; blocks count to GRID

// ---------------------------------------------------------------------------
// Fused kernel.
//  blocks 0..15 (4 warps each): warp w = one batch row b. Compute 8 logits
//    (feat value loaded once per lane, reused across all 8 bands), softmax,
//    publish g_bw[b], bump g_ready.
//  all blocks: compute 4 band indices (weight-independent), spin on g_ready,
//    load the 64x9 LUT to smem (slot 8 = 0 handles the r==max_r pixel),
//    then stream 64 float4 stores per thread with __stcs.
//  last block to finish resets g_ready/g_done for the next graph replay.
// ---------------------------------------------------------------------------
__global__ void __launch_bounds__(TPB) fused_freqmask_kernel(
        const float* __restrict__ feat,
        const float* __restrict__ wmat,
        const float* __restrict__ bias,
        float* __restrict__ out) {

    const int lane = threadIdx.x & 31;
    const int warp = threadIdx.x >> 5;

    // ---------------- producer: blocks 0..15, one warp per batch row -------
    if (blockIdx.x < 16) {
        const int b = blockIdx.x * 4 + warp;      // 0..63
        const float* f = feat + b * FEAT;

        float acc[NB];
        #pragma unroll
        for (int i = 0; i < NB; i++) acc[i] = 0.0f;

        #pragma unroll
        for (int k = lane; k < FEAT; k += 32) {
            float fv = f[k];
            #pragma unroll
            for (int i = 0; i < NB; i++)
                acc[i] += fv * wmat[i * FEAT + k];
        }
        #pragma unroll
        for (int i = 0; i < NB; i++)
            #pragma unroll
            for (int o = 16; o; o >>= 1)
                acc[i] += __shfl_down_sync(0xffffffffu, acc[i], o);

        if (lane == 0) {
            float lg[NB];
            float m = -1e30f;
            #pragma unroll
            for (int i = 0; i < NB; i++) {
                lg[i] = acc[i] + bias[i];
                m = fmaxf(m, lg[i]);
            }
            float s = 0.0f;
            #pragma unroll
            for (int i = 0; i < NB; i++) {
                lg[i] = expf(lg[i] - m);
                s += lg[i];
            }
            float inv = 1.0f / s;
            #pragma unroll
            for (int i = 0; i < NB; i++)
                g_bw[b * NB + i] = lg[i] * inv;
            __threadfence();
            atomicAdd(&g_ready, 1);
        }
    }

    // ---------------- band indices (independent of weights) ----------------
    const int base = (blockIdx.x * TPB + threadIdx.x) * 4;   // always < HWR
    const float max_r = sqrtf(0.5f);                          // bit-exact

    int band[4];
    #pragma unroll
    for (int j = 0; j < 4; j++) {
        int p  = base + j;
        int h  = p / WR;
        int wc = p - h * WR;
        float u = (float)wc * (1.0f / 1024.0f);
        float v = (float)(h < H_SZ / 2 ? h : h - H_SZ) * (1.0f / 1024.0f);
        float r = sqrtf(u * u + v * v);                       // exact args

        int bi = 0;
        #pragma unroll
        for (int i = 1; i < NB; i++)
            bi += (r >= max_r * ((float)i / (float)NB)) ? 1 : 0;
        band[j] = (r >= max_r) ? 8 : bi;                      // 8 -> zero slot
    }

    // ---------------- wait for all 64 producer rows ------------------------
    if (threadIdx.x == 0) {
        while (*(volatile int*)&g_ready != B_SZ)
            __nanosleep(64);
    }
    __syncthreads();
    __threadfence();   // acquire: order LUT loads after flag observation

    __shared__ float bw[B_SZ * 9];
    for (int i = threadIdx.x; i < B_SZ * 9; i += TPB) {
        int b = i / 9, s = i - b * 9;
        bw[i] = (s < NB) ? g_bw[b * NB + s] : 0.0f;
    }
    __syncthreads();

    // ---------------- streaming stores: 64 planes x float4 -----------------
    float* o = out + base;
    #pragma unroll 4
    for (int b = 0; b < B_SZ; b++) {
        const float* row = bw + b * 9;
        float4 v4;
        v4.x = row[band[0]];
        v4.y = row[band[1]];
        v4.z = row[band[2]];
        v4.w = row[band[3]];
        __stcs(reinterpret_cast<float4*>(o + (size_t)b * HWR), v4);
    }

    // ---------------- reset handshake state for next graph replay ----------
    __syncthreads();
    if (threadIdx.x == 0) {
        int d = atomicAdd(&g_done, 1);
        if (d == (int)gridDim.x - 1) {
            g_ready = 0;
            g_done  = 0;
            __threadfence();
        }
    }
}

// ---------------------------------------------------------------------------
extern "C" void kernel_launch(void* const* d_in, const int* in_sizes, int n_in,
                              void* d_out, int out_size) {
    const float* feat = (const float*)d_in[0];  // [64, 512]
    const float* w    = (const float*)d_in[1];  // [8, 512]
    const float* bias = (const float*)d_in[2];  // [8]
    float* out = (float*)d_out;                 // [64, 1, 1024, 513] fp32

    fused_freqmask_kernel<<<GRID, TPB>>>(feat, w, bias, out);
}